// round 7
// baseline (speedup 1.0000x reference)
#include <cuda_runtime.h>

#define BDIM 512
#define FDIM 1024
#define H1D  512
#define H2D  256
#define OUTD 128
#define KDD  5
#define NMD  (OUTD*KDD)   // 640
#define LOG2E 1.44269504f

// Scratch (device globals)
__device__ float g_h1p[8 * BDIM * H1D];    // GEMM1 partials (split-K=8)
__device__ float g_h1 [BDIM * H1D];        // reduced + lrelu
__device__ float g_h2p[8 * BDIM * H2D];    // GEMM2 partials (split-K=8)
__device__ float g_h2 [BDIM * H2D];        // reduced + lrelu
__device__ float g_Mp [2 * BDIM * NMD];    // GEMM3 partials (split-K=2)
__device__ float g_obp[4 * OUTD * BDIM];   // pairwise partials [split][o][j]
__device__ float g_z3p[6 * BDIM * OUTD];   // GEMM4 partials (4 h2 + 2 ob)

__device__ __forceinline__ float lrelu(float v) { return fmaxf(v, 0.2f * v); }

#define FMA2(c, a, b) asm("fma.rn.f32x2 %0, %1, %2, %0;" : "+l"(c) : "l"(a), "l"(b))
#define SPLAT(d, x)   asm("mov.b64 %0, {%1, %1};" : "=l"(d) : "f"(x))

// ---------------------------------------------------------------------------
// SIMT GEMM, 128(M) x 64(N) tile, 256 threads (8 warps = 2 per SMSP), BK=16,
// 4(m) x 8(n) microtile in packed f32x2 (16 FFMA2/kk/thread).
// 2 warps/SMSP gives cross-warp latency hiding; double-buffered smem with
// register prefetch keeps LDG off the critical path.
// OB=1: A is the k-major [k][m] pairwise-partial layout (ld=512); the A-load
// sums NPART partials and subtracts 1. Otherwise A is a plain row-major matrix.
// ---------------------------------------------------------------------------
template<int NPART, int OB>
__global__ __launch_bounds__(256)
void gemm_k(const float* __restrict__ Abase, int apStride,
            const float* __restrict__ Bm,
            float* __restrict__ Cpart, int cpStride,
            int Kc, int lda, int ldb, int ldc)
{
    __shared__ float As[2][16][132];   // [buf][k][m]
    __shared__ float Bs[2][16][68];    // [buf][k][n]

    const int tid  = threadIdx.x;
    const int tn   = (tid & 7) * 8;    // 8 contiguous cols
    const int tm   = (tid >> 3) * 4;   // 4 contiguous rows (0..124)
    const int row0 = blockIdx.y * 128;
    const int col0 = blockIdx.x * 64;
    const int k0   = blockIdx.z * Kc;

    float4 pa[2], pb;                  // prefetch registers

    auto fetch = [&](int kbase) {
        #pragma unroll
        for (int i = 0; i < 2; i++) {
            int f = tid + i * 256;
            if (!OB) {
                int r = f >> 2, kq = (f & 3) * 4;
                pa[i] = *(const float4*)(Abase + (size_t)(row0 + r) * lda + kbase + kq);
            } else {
                int kk = f >> 5, mq = (f & 31) * 4;
                const float* ap = Abase + (size_t)(kbase + kk) * BDIM + row0 + mq;
                float4 v = *(const float4*)ap;
                #pragma unroll
                for (int p = 1; p < NPART; p++) {
                    float4 u = *(const float4*)(ap + (size_t)p * apStride);
                    v.x += u.x; v.y += u.y; v.z += u.z; v.w += u.w;
                }
                v.x -= 1.0f; v.y -= 1.0f; v.z -= 1.0f; v.w -= 1.0f;
                pa[i] = v;
            }
        }
        int kk = tid >> 4, nq = (tid & 15) * 4;
        pb = *(const float4*)(Bm + (size_t)(kbase + kk) * ldb + col0 + nq);
    };
    auto stick = [&](int buf) {
        #pragma unroll
        for (int i = 0; i < 2; i++) {
            int f = tid + i * 256;
            if (!OB) {
                int r = f >> 2, kq = (f & 3) * 4;
                As[buf][kq + 0][r] = pa[i].x;
                As[buf][kq + 1][r] = pa[i].y;
                As[buf][kq + 2][r] = pa[i].z;
                As[buf][kq + 3][r] = pa[i].w;
            } else {
                int kk = f >> 5, mq = (f & 31) * 4;
                *(float4*)&As[buf][kk][mq] = pa[i];
            }
        }
        int kk = tid >> 4, nq = (tid & 15) * 4;
        *(float4*)&Bs[buf][kk][nq] = pb;
    };

    unsigned long long acc[4][4] = {};   // [m][n-pair]

    fetch(k0);
    stick(0);
    __syncthreads();

    for (int kt = 0; kt < Kc; kt += 16) {
        const int  cur = (kt >> 4) & 1;
        const bool nxt = (kt + 16) < Kc;
        if (nxt) fetch(k0 + kt + 16);

        #pragma unroll
        for (int kk = 0; kk < 16; kk++) {
            float4 a = *(const float4*)&As[cur][kk][tm];
            ulonglong2 b0 = *(const ulonglong2*)&Bs[cur][kk][tn];
            ulonglong2 b1 = *(const ulonglong2*)&Bs[cur][kk][tn + 4];
            unsigned long long bp[4] = {b0.x, b0.y, b1.x, b1.y};
            float av[4] = {a.x, a.y, a.z, a.w};
            unsigned long long as_[4];
            #pragma unroll
            for (int mi = 0; mi < 4; mi++) SPLAT(as_[mi], av[mi]);
            #pragma unroll
            for (int mi = 0; mi < 4; mi++)
                #pragma unroll
                for (int nj = 0; nj < 4; nj++)
                    FMA2(acc[mi][nj], as_[mi], bp[nj]);
        }
        if (nxt) stick(cur ^ 1);
        __syncthreads();
    }

    float* cp = Cpart + (size_t)blockIdx.z * cpStride;
    #pragma unroll
    for (int mi = 0; mi < 4; mi++) {
        int row = row0 + tm + mi;
        ulonglong2 v0, v1;
        v0.x = acc[mi][0]; v0.y = acc[mi][1];
        v1.x = acc[mi][2]; v1.y = acc[mi][3];
        *(ulonglong2*)&cp[(size_t)row * ldc + col0 + tn]     = v0;
        *(ulonglong2*)&cp[(size_t)row * ldc + col0 + tn + 4] = v1;
    }
}

// ---------------------------------------------------------------------------
// Reduce NP split-K partials + bias + leaky-relu. One float4 per thread.
// NCOLS is the row width (bias period). Fully parallel, trivially fast.
// ---------------------------------------------------------------------------
template<int NP, int NCOLS>
__global__ __launch_bounds__(256)
void reduce_act(const float* __restrict__ P, int pStride,
                const float* __restrict__ bias, float* __restrict__ Out)
{
    int f = (blockIdx.x * 256 + threadIdx.x) * 4;
    const float* p = P + f;
    float4 v = *(const float4*)p;
    #pragma unroll
    for (int i = 1; i < NP; i++) {
        float4 u = *(const float4*)(p + (size_t)i * pStride);
        v.x += u.x; v.y += u.y; v.z += u.z; v.w += u.w;
    }
    float4 bv = *(const float4*)(bias + (f & (NCOLS - 1)));
    v.x = lrelu(v.x + bv.x);
    v.y = lrelu(v.y + bv.y);
    v.z = lrelu(v.z + bv.z);
    v.w = lrelu(v.w + bv.w);
    *(float4*)(Out + f) = v;
}

// ---------------------------------------------------------------------------
// Pairwise minibatch discrimination, split over i into 4 chunks of 128.
// grid (o=128, split=4), 512 threads (one per j). Sums 2 M split-K partials
// at load and pre-scales by log2e so the inner loop is pure EX2.
// ---------------------------------------------------------------------------
__global__ __launch_bounds__(512)
void pairwise_k(const float* __restrict__ Mp, float* __restrict__ obp)
{
    __shared__ float s[128 * 8];
    const int o  = blockIdx.x;
    const int sp = blockIdx.y;
    const int j  = threadIdx.x;
    const int i0 = sp * 128;
    const size_t MS = (size_t)BDIM * NMD;

    for (int idx = j; idx < 128 * KDD; idx += 512) {
        int i = idx / KDD, k = idx - i * KDD;
        const float* p = Mp + (size_t)(i0 + i) * NMD + o * KDD + k;
        s[i * 8 + k] = (p[0] + p[MS]) * LOG2E;
    }
    const float* pj = Mp + (size_t)j * NMD + o * KDD;
    float mj[KDD];
    #pragma unroll
    for (int k = 0; k < KDD; k++)
        mj[k] = (pj[k] + pj[k + MS]) * LOG2E;
    __syncthreads();

    float acc0 = 0.f, acc1 = 0.f;
    #pragma unroll 16
    for (int i = 0; i < 128; i++) {
        float4 v = *(const float4*)&s[i * 8];
        float  w = s[i * 8 + 4];
        float n = fabsf(v.x - mj[0]) + fabsf(v.y - mj[1]) + fabsf(v.z - mj[2])
                + fabsf(v.w - mj[3]) + fabsf(w - mj[4]);
        float e;
        asm("ex2.approx.f32 %0, %1;" : "=f"(e) : "f"(-n));
        if (i & 1) acc1 += e; else acc0 += e;
    }
    obp[(size_t)sp * (OUTD * BDIM) + o * BDIM + j] = acc0 + acc1;
}

// ---------------------------------------------------------------------------
// Final: z3 = lrelu(sum of 6 GEMM4 partials + b3); out = z3 @ W4 + b4.
// ---------------------------------------------------------------------------
__global__ __launch_bounds__(256)
void final_k(const float* __restrict__ z3p, const float* __restrict__ b3,
             const float* __restrict__ W4, const float* __restrict__ b4,
             float* __restrict__ out)
{
    const size_t ZS = (size_t)BDIM * OUTD;
    int gw   = (blockIdx.x * 256 + threadIdx.x) >> 5;
    int lane = threadIdx.x & 31;
    float sum = 0.f;
    #pragma unroll
    for (int it = 0; it < 4; it++) {
        int k = it * 32 + lane;
        const float* p = z3p + (size_t)gw * OUTD + k;
        float v = ((p[0] + p[ZS]) + (p[2 * ZS] + p[3 * ZS]))
                + (p[4 * ZS] + p[5 * ZS]) + b3[k];
        v = lrelu(v);
        sum += v * W4[k];
    }
    #pragma unroll
    for (int off = 16; off; off >>= 1)
        sum += __shfl_xor_sync(0xffffffffu, sum, off);
    if (lane == 0) out[gw] = sum + b4[0];
}

// ---------------------------------------------------------------------------
extern "C" void kernel_launch(void* const* d_in, const int* in_sizes, int n_in,
                              void* d_out, int out_size)
{
    (void)in_sizes; (void)n_in; (void)out_size;
    const float* x  = (const float*)d_in[0];
    const float* W1 = (const float*)d_in[1];
    const float* b1 = (const float*)d_in[2];
    const float* W2 = (const float*)d_in[3];
    const float* b2 = (const float*)d_in[4];
    const float* T  = (const float*)d_in[5];
    const float* W3 = (const float*)d_in[6];
    const float* b3 = (const float*)d_in[7];
    const float* W4 = (const float*)d_in[8];
    const float* b4 = (const float*)d_in[9];
    float* out = (float*)d_out;

    float *h1p, *h1, *h2p, *h2, *Mp, *obp, *z3p;
    cudaGetSymbolAddress((void**)&h1p, g_h1p);
    cudaGetSymbolAddress((void**)&h1,  g_h1);
    cudaGetSymbolAddress((void**)&h2p, g_h2p);
    cudaGetSymbolAddress((void**)&h2,  g_h2);
    cudaGetSymbolAddress((void**)&Mp,  g_Mp);
    cudaGetSymbolAddress((void**)&obp, g_obp);
    cudaGetSymbolAddress((void**)&z3p, g_z3p);

    // GEMM1: x @ W1 -> h1p, split-K=8 (Kc=128) -> 8x4x8 = 256 blocks
    gemm_k<1,0><<<dim3(8,4,8), 256>>>(x, 0, W1, h1p, BDIM*H1D, 128, FDIM, H1D, H1D);
    // h1 = lrelu(sum8 + b1): 512x512/4 = 65536 float4 -> 256 blocks
    reduce_act<8, H1D><<<256, 256>>>(h1p, BDIM*H1D, b1, h1);
    // GEMM2: h1 @ W2 -> h2p, split-K=8 (Kc=64) -> 4x4x8 = 128 blocks
    gemm_k<1,0><<<dim3(4,4,8), 256>>>(h1, 0, W2, h2p, BDIM*H2D, 64, H1D, H2D, H2D);
    // h2 = lrelu(sum8 + b2): 512x256/4 = 32768 float4 -> 128 blocks
    reduce_act<8, H2D><<<128, 256>>>(h2p, BDIM*H2D, b2, h2);
    // GEMM3: h2 @ T -> Mp, split-K=2 (Kc=128) -> 10x4x2 = 80 blocks
    gemm_k<1,0><<<dim3(10,4,2), 256>>>(h2, 0, T, Mp, BDIM*NMD, 128, H2D, NMD, NMD);
    // GEMM4a: h2 @ W3[:256] -> z3p[0..3], split-K=4 (Kc=64) -> 2x4x4 = 32 blocks
    gemm_k<1,0><<<dim3(2,4,4), 256>>>(h2, 0, W3, z3p, BDIM*OUTD, 64, H2D, OUTD, OUTD);
    // Pairwise: o_b partials, grid (128 o, 4 i-chunks) = 512 blocks
    pairwise_k<<<dim3(OUTD, 4), BDIM>>>(Mp, obp);
    // GEMM4b: (sum4 ob partials - 1) @ W3[256:] -> z3p[4..5], split-K=2 -> 2x4x2 = 16 blocks
    gemm_k<4,1><<<dim3(2,4,2), 256>>>(obp, OUTD*BDIM, W3 + 256*OUTD,
                                      z3p + 4*(size_t)BDIM*OUTD, BDIM*OUTD,
                                      64, 0, OUTD, OUTD);
    // Final: lrelu(sum6 z3 partials + b3) @ W4 + b4
    final_k<<<64, 256>>>(z3p, b3, W4, b4, out);
}

// round 8
// speedup vs baseline: 1.0406x; 1.0406x over previous
#include <cuda_runtime.h>

#define BDIM 512
#define FDIM 1024
#define H1D  512
#define H2D  256
#define OUTD 128
#define KDD  5
#define NMD  (OUTD*KDD)   // 640
#define LOG2E 1.44269504f
#define NB   296          // 2 blocks per SM on 148 SMs (all co-resident)

// Scratch (device globals)
__device__ float g_h1p[8 * BDIM * H1D];    // GEMM1 partials (split-K=8)
__device__ float g_h1 [BDIM * H1D];
__device__ float g_h2p[8 * BDIM * H2D];    // GEMM2 partials (split-K=8)
__device__ float g_h2 [BDIM * H2D];
__device__ float g_Mp [4 * BDIM * NMD];    // GEMM3 partials (split-K=4)
__device__ float g_obp[2 * OUTD * BDIM];   // pairwise partials [isplit][o][j]
__device__ float g_z3p[6 * BDIM * OUTD];   // GEMM4 partials (4 h2 + 2 ob)

__device__ unsigned g_barcount = 0;
__device__ volatile unsigned g_bargen = 0;

__device__ __forceinline__ float lrelu(float v) { return fmaxf(v, 0.2f * v); }

#define FMA2(c, a, b) asm("fma.rn.f32x2 %0, %1, %2, %0;" : "+l"(c) : "l"(a), "l"(b))
#define SPLAT(d, x)   asm("mov.b64 %0, {%1, %1};" : "=l"(d) : "f"(x))

// Sense-reversing grid barrier. All NB blocks are co-resident (launch_bounds
// guarantees 2 blocks/SM), so spinning is safe. Counter wraps to 0 every
// barrier (atomicInc), generation just grows -> deterministic across replays.
__device__ __forceinline__ void grid_barrier()
{
    __syncthreads();
    if (threadIdx.x == 0) {
        unsigned gen = g_bargen;
        __threadfence();
        if (atomicInc(&g_barcount, NB - 1) == NB - 1) {
            __threadfence();
            g_bargen = gen + 1;
        } else {
            while (g_bargen == gen) __nanosleep(64);
            __threadfence();
        }
    }
    __syncthreads();
}

// ---------------------------------------------------------------------------
// One 128(M) x 64(N) x Kc GEMM tile, 256 threads, BK=16, 4m x 8n f32x2
// microtile, double-buffered smem with register prefetch.
// sA: [2][16][132] floats, sB: [2][16][68] floats (caller-provided smem).
// OB=1: A is the k-major [k][m] layout (ld=512); sum NPART partials, -1.
// ---------------------------------------------------------------------------
template<int OB, int NPART>
__device__ void gemm_tile(float* sA, float* sB,
                          int ux, int uy, int uz,
                          const float* __restrict__ Abase, size_t apStride,
                          const float* __restrict__ Bm,
                          float* __restrict__ Cpart, size_t cpStride,
                          int Kc, int lda, int ldb, int ldc)
{
    const int tid  = threadIdx.x;
    const int tn   = (tid & 7) * 8;
    const int tm   = (tid >> 3) * 4;
    const int row0 = uy * 128;
    const int col0 = ux * 64;
    const int k0   = uz * Kc;

    float4 pa[2], pb;

    auto fetch = [&](int kbase) {
        #pragma unroll
        for (int i = 0; i < 2; i++) {
            int f = tid + i * 256;
            if (!OB) {
                int r = f >> 2, kq = (f & 3) * 4;
                pa[i] = *(const float4*)(Abase + (size_t)(row0 + r) * lda + kbase + kq);
            } else {
                int kk = f >> 5, mq = (f & 31) * 4;
                const float* ap = Abase + (size_t)(kbase + kk) * BDIM + row0 + mq;
                float4 v = *(const float4*)ap;
                #pragma unroll
                for (int p = 1; p < NPART; p++) {
                    float4 u = *(const float4*)(ap + (size_t)p * apStride);
                    v.x += u.x; v.y += u.y; v.z += u.z; v.w += u.w;
                }
                v.x -= 1.0f; v.y -= 1.0f; v.z -= 1.0f; v.w -= 1.0f;
                pa[i] = v;
            }
        }
        int kk = tid >> 4, nq = (tid & 15) * 4;
        pb = *(const float4*)(Bm + (size_t)(kbase + kk) * ldb + col0 + nq);
    };
    auto stick = [&](int buf) {
        float* A_ = sA + buf * 2112;
        #pragma unroll
        for (int i = 0; i < 2; i++) {
            int f = tid + i * 256;
            if (!OB) {
                int r = f >> 2, kq = (f & 3) * 4;
                A_[(kq + 0) * 132 + r] = pa[i].x;
                A_[(kq + 1) * 132 + r] = pa[i].y;
                A_[(kq + 2) * 132 + r] = pa[i].z;
                A_[(kq + 3) * 132 + r] = pa[i].w;
            } else {
                int kk = f >> 5, mq = (f & 31) * 4;
                *(float4*)&A_[kk * 132 + mq] = pa[i];
            }
        }
        int kk = tid >> 4, nq = (tid & 15) * 4;
        *(float4*)&sB[buf * 1088 + kk * 68 + nq] = pb;
    };

    unsigned long long acc[4][4] = {};

    fetch(k0);
    __syncthreads();          // smem may be in use by the previous unit/phase
    stick(0);
    __syncthreads();

    for (int kt = 0; kt < Kc; kt += 16) {
        const int  cur = (kt >> 4) & 1;
        const bool nxt = (kt + 16) < Kc;
        if (nxt) fetch(k0 + kt + 16);

        const float* A_ = sA + cur * 2112;
        const float* B_ = sB + cur * 1088;
        #pragma unroll
        for (int kk = 0; kk < 16; kk++) {
            float4 a = *(const float4*)&A_[kk * 132 + tm];
            ulonglong2 b0 = *(const ulonglong2*)&B_[kk * 68 + tn];
            ulonglong2 b1 = *(const ulonglong2*)&B_[kk * 68 + tn + 4];
            unsigned long long bp[4] = {b0.x, b0.y, b1.x, b1.y};
            float av[4] = {a.x, a.y, a.z, a.w};
            unsigned long long as_[4];
            #pragma unroll
            for (int mi = 0; mi < 4; mi++) SPLAT(as_[mi], av[mi]);
            #pragma unroll
            for (int mi = 0; mi < 4; mi++)
                #pragma unroll
                for (int nj = 0; nj < 4; nj++)
                    FMA2(acc[mi][nj], as_[mi], bp[nj]);
        }
        if (nxt) stick(cur ^ 1);
        __syncthreads();
    }

    float* cp = Cpart + (size_t)uz * cpStride;
    #pragma unroll
    for (int mi = 0; mi < 4; mi++) {
        int row = row0 + tm + mi;
        ulonglong2 v0, v1;
        v0.x = acc[mi][0]; v0.y = acc[mi][1];
        v1.x = acc[mi][2]; v1.y = acc[mi][3];
        *(ulonglong2*)&cp[(size_t)row * ldc + col0 + tn]     = v0;
        *(ulonglong2*)&cp[(size_t)row * ldc + col0 + tn + 4] = v1;
    }
}

// Reduce 8 split-K partials + bias + leaky-relu for one float4.
template<int NCOLS>
__device__ __forceinline__ void reduce8(const float* __restrict__ P, size_t st,
                                        const float* __restrict__ bias,
                                        float* __restrict__ Out, int idx)
{
    int f = idx * 4;
    const float* p = P + f;
    float4 v = *(const float4*)p;
    #pragma unroll
    for (int i = 1; i < 8; i++) {
        float4 u = *(const float4*)(p + (size_t)i * st);
        v.x += u.x; v.y += u.y; v.z += u.z; v.w += u.w;
    }
    float4 bv = *(const float4*)(bias + (f & (NCOLS - 1)));
    v.x = lrelu(v.x + bv.x);
    v.y = lrelu(v.y + bv.y);
    v.z = lrelu(v.z + bv.z);
    v.w = lrelu(v.w + bv.w);
    *(float4*)(Out + f) = v;
}

// One pairwise unit: (o, j-half, i-chunk of 256). 256 threads.
__device__ void pairwise_unit(float* s, int u)
{
    const int o   = u & 127;
    const int jh  = (u >> 7) & 1;
    const int isp = u >> 8;
    const int tid = threadIdx.x;
    const int i0  = isp * 256;
    const size_t MS = (size_t)BDIM * NMD;

    __syncthreads();   // protect smem reuse across units/phases
    #pragma unroll
    for (int it = 0; it < 5; it++) {
        int idx = tid + it * 256;              // 0..1279 = 256*5
        int i = idx / 5, k = idx - i * 5;
        const float* p = g_Mp + (size_t)(i0 + i) * NMD + o * KDD + k;
        s[i * 8 + k] = (p[0] + p[MS] + p[2 * MS] + p[3 * MS]) * LOG2E;
    }
    const int j = jh * 256 + tid;
    const float* pj = g_Mp + (size_t)j * NMD + o * KDD;
    float mj[KDD];
    #pragma unroll
    for (int k = 0; k < KDD; k++)
        mj[k] = (pj[k] + pj[k + MS] + pj[k + 2 * MS] + pj[k + 3 * MS]) * LOG2E;
    __syncthreads();

    float acc0 = 0.f, acc1 = 0.f;
    #pragma unroll 16
    for (int i = 0; i < 256; i++) {
        float4 v = *(const float4*)&s[i * 8];
        float  w = s[i * 8 + 4];
        float n = fabsf(v.x - mj[0]) + fabsf(v.y - mj[1]) + fabsf(v.z - mj[2])
                + fabsf(v.w - mj[3]) + fabsf(w - mj[4]);
        float e;
        asm("ex2.approx.f32 %0, %1;" : "=f"(e) : "f"(-n));
        if (i & 1) acc1 += e; else acc0 += e;
    }
    g_obp[(size_t)isp * (OUTD * BDIM) + o * BDIM + j] = acc0 + acc1;
}

// ---------------------------------------------------------------------------
// Persistent megakernel: all phases, grid barriers between them.
// ---------------------------------------------------------------------------
__global__ __launch_bounds__(256, 2)
void mega(const float* __restrict__ x,  const float* __restrict__ W1,
          const float* __restrict__ b1, const float* __restrict__ W2,
          const float* __restrict__ b2, const float* __restrict__ T,
          const float* __restrict__ W3, const float* __restrict__ b3,
          const float* __restrict__ W4, const float* __restrict__ b4,
          float* __restrict__ out)
{
    __shared__ float sm[2 * 16 * 132 + 2 * 16 * 68];   // 25.6 KB
    float* sA = sm;
    float* sB = sm + 2 * 16 * 132;
    const int bid = blockIdx.x;
    const int tid = threadIdx.x;

    // P1: GEMM1 x@W1 -> h1p, split-K=8 (Kc=128): 8x4x8 = 256 units
    for (int u = bid; u < 256; u += NB) {
        int ux = u & 7, uy = (u >> 3) & 3, uz = u >> 5;
        gemm_tile<0,1>(sA, sB, ux, uy, uz, x, 0, W1,
                       g_h1p, (size_t)BDIM * H1D, 128, FDIM, H1D, H1D);
    }
    grid_barrier();

    // P2: h1 = lrelu(sum8 + b1)
    {
        int idx = bid * 256 + tid;
        if (idx < BDIM * H1D / 4)
            reduce8<H1D>(g_h1p, (size_t)BDIM * H1D, b1, g_h1, idx);
    }
    grid_barrier();

    // P3: GEMM2 h1@W2 -> h2p, split-K=8 (Kc=64): 4x4x8 = 128 units
    for (int u = bid; u < 128; u += NB) {
        int ux = u & 3, uy = (u >> 2) & 3, uz = u >> 4;
        gemm_tile<0,1>(sA, sB, ux, uy, uz, g_h1, 0, W2,
                       g_h2p, (size_t)BDIM * H2D, 64, H1D, H2D, H2D);
    }
    grid_barrier();

    // P4: h2 = lrelu(sum8 + b2)
    {
        int idx = bid * 256 + tid;
        if (idx < BDIM * H2D / 4)
            reduce8<H2D>(g_h2p, (size_t)BDIM * H2D, b2, g_h2, idx);
    }
    grid_barrier();

    // P5: GEMM3 h2@T -> Mp (split-K=4, 10x4x4 = 160 units)
    //     + GEMM4a h2@W3[:256] -> z3p[0..3] (split-K=4, 2x4x4 = 32 units)
    for (int u = bid; u < 192; u += NB) {
        if (u < 160) {
            int ux = u % 10, uy = (u / 10) & 3, uz = u / 40;
            gemm_tile<0,1>(sA, sB, ux, uy, uz, g_h2, 0, T,
                           g_Mp, (size_t)BDIM * NMD, 64, H2D, NMD, NMD);
        } else {
            int v = u - 160;
            int ux = v & 1, uy = (v >> 1) & 3, uz = v >> 3;
            gemm_tile<0,1>(sA, sB, ux, uy, uz, g_h2, 0, W3,
                           g_z3p, (size_t)BDIM * OUTD, 64, H2D, OUTD, OUTD);
        }
    }
    grid_barrier();

    // P6: pairwise -> obp, 512 units (o x j-half x i-chunk)
    for (int u = bid; u < 512; u += NB)
        pairwise_unit(sm, u);
    grid_barrier();

    // P7: GEMM4b (sum2 obp - 1)@W3[256:] -> z3p[4..5], split-K=2: 2x4x2 = 16 units
    for (int u = bid; u < 16; u += NB) {
        int ux = u & 1, uy = (u >> 1) & 3, uz = u >> 3;
        gemm_tile<1,2>(sA, sB, ux, uy, uz, g_obp, (size_t)OUTD * BDIM,
                       W3 + 256 * OUTD,
                       g_z3p + 4 * (size_t)BDIM * OUTD, (size_t)BDIM * OUTD,
                       64, 0, OUTD, OUTD);
    }
    grid_barrier();

    // P8: final — z3 = lrelu(sum6 z3p + b3); out = z3@W4 + b4. One warp/row.
    if (bid < 64) {
        const size_t ZS = (size_t)BDIM * OUTD;
        int gw   = bid * 8 + (tid >> 5);
        int lane = tid & 31;
        float sum = 0.f;
        #pragma unroll
        for (int it = 0; it < 4; it++) {
            int k = it * 32 + lane;
            const float* p = g_z3p + (size_t)gw * OUTD + k;
            float v = ((p[0] + p[ZS]) + (p[2 * ZS] + p[3 * ZS]))
                    + (p[4 * ZS] + p[5 * ZS]) + b3[k];
            v = lrelu(v);
            sum += v * W4[k];
        }
        #pragma unroll
        for (int off = 16; off; off >>= 1)
            sum += __shfl_xor_sync(0xffffffffu, sum, off);
        if (lane == 0) out[gw] = sum + b4[0];
    }
}

// ---------------------------------------------------------------------------
extern "C" void kernel_launch(void* const* d_in, const int* in_sizes, int n_in,
                              void* d_out, int out_size)
{
    (void)in_sizes; (void)n_in; (void)out_size;
    mega<<<NB, 256>>>((const float*)d_in[0], (const float*)d_in[1],
                      (const float*)d_in[2], (const float*)d_in[3],
                      (const float*)d_in[4], (const float*)d_in[5],
                      (const float*)d_in[6], (const float*)d_in[7],
                      (const float*)d_in[8], (const float*)d_in[9],
                      (float*)d_out);
}